// round 15
// baseline (speedup 1.0000x reference)
#include <cuda_runtime.h>
#include <cuda_bf16.h>
#include <math.h>

#define BSZ 4096
#define DIM 128

// Scratch (no allocs allowed anywhere).
__device__ float g_S[(size_t)BSZ * BSZ];
__device__ float g_row[BSZ];
__device__ int   g_valid[BSZ];
__device__ __nv_bfloat16 g_Fhi[(size_t)BSZ * DIM];
__device__ __nv_bfloat16 g_Flo[(size_t)BSZ * DIM];
__device__ int g_done;   // zero-init; self-resetting last-block counter

// ---------------- Kernel 0: fp32 -> bf16 hi/lo split ----------------
__global__ __launch_bounds__(256) void convert_kernel(const float* __restrict__ F) {
    int idx = blockIdx.x * 256 + threadIdx.x;
    float4 v = ((const float4*)F)[idx];
    float vs[4] = {v.x, v.y, v.z, v.w};
    __nv_bfloat16 h[4], l[4];
#pragma unroll
    for (int e = 0; e < 4; e++) {
        h[e] = __float2bfloat16(vs[e]);
        l[e] = __float2bfloat16(vs[e] - __bfloat162float(h[e]));
    }
    __nv_bfloat162* ph = (__nv_bfloat162*)g_Fhi + idx * 2;
    __nv_bfloat162* pl = (__nv_bfloat162*)g_Flo + idx * 2;
    ph[0] = __halves2bfloat162(h[0], h[1]);
    ph[1] = __halves2bfloat162(h[2], h[3]);
    pl[0] = __halves2bfloat162(l[0], l[1]);
    pl[1] = __halves2bfloat162(l[2], l[3]);
}

// ---------------- mma.sync / cp.async helpers (sm_80 PTX, sm_103-legal) ---
__device__ __forceinline__ void ldsm4(unsigned& r0, unsigned& r1,
                                      unsigned& r2, unsigned& r3, unsigned addr) {
    asm volatile("ldmatrix.sync.aligned.m8n8.x4.shared.b16 {%0,%1,%2,%3}, [%4];"
                 : "=r"(r0), "=r"(r1), "=r"(r2), "=r"(r3) : "r"(addr));
}
__device__ __forceinline__ void mma16816(float* d, const unsigned* a, const unsigned* b) {
    asm volatile(
        "mma.sync.aligned.m16n8k16.row.col.f32.bf16.bf16.f32 "
        "{%0,%1,%2,%3},{%4,%5,%6,%7},{%8,%9},{%0,%1,%2,%3};"
        : "+f"(d[0]), "+f"(d[1]), "+f"(d[2]), "+f"(d[3])
        : "r"(a[0]), "r"(a[1]), "r"(a[2]), "r"(a[3]), "r"(b[0]), "r"(b[1]));
}
__device__ __forceinline__ void cp16(unsigned dst, const void* src) {
    asm volatile("cp.async.ca.shared.global [%0], [%1], 16;" :: "r"(dst), "l"(src));
}
__device__ __forceinline__ void cp_commit() {
    asm volatile("cp.async.commit_group;");
}
template <int N>
__device__ __forceinline__ void cp_wait() {
    asm volatile("cp.async.wait_group %0;" :: "n"(N));
}

// ------- Kernel 1: S = F F^T upper-tri via HMMA + epilogue mirror ---------
#define KCH 32
#define TLD 40
#define ARR_BYTES (128 * TLD * 2)       // 10240
#define STAGE_BYTES (4 * ARR_BYTES)     // 40960
#define SMEM_GEMM (2 * STAGE_BYTES)     // 81920 (>= 128*133*4 = 68096 staging)

__global__ __launch_bounds__(256, 2) void gemm_mma_kernel() {
    extern __shared__ __nv_bfloat16 smem[];

    if (blockIdx.y > blockIdx.x) return;   // upper-triangular tiles only

    const int tid = threadIdx.x;
    const int wid = tid >> 5;
    const int lane = tid & 31;
    const int i0 = blockIdx.y * 128;
    const int j0 = blockIdx.x * 128;
    const int m_off = (wid >> 2) * 64;
    const int n_off = (wid & 3) * 32;

    const unsigned sb = (unsigned)__cvta_generic_to_shared(smem);

    const int l_row = tid >> 1;
    const int l_c   = (tid & 1) * 2;
    auto load_chunk = [&](int st, int kc) {
        unsigned base = sb + st * STAGE_BYTES;
#pragma unroll
        for (int cc = 0; cc < 2; cc++) {
            int c = l_c + cc;
            unsigned so = (unsigned)(l_row * TLD + c * 8) * 2;
            int ga = (i0 + l_row) * DIM + kc + c * 8;
            int gb = (j0 + l_row) * DIM + kc + c * 8;
            cp16(base + so,                 g_Fhi + ga);
            cp16(base + ARR_BYTES + so,     g_Flo + ga);
            cp16(base + 2 * ARR_BYTES + so, g_Fhi + gb);
            cp16(base + 3 * ARR_BYTES + so, g_Flo + gb);
        }
        cp_commit();
    };

    float acc[4][4][4];
#pragma unroll
    for (int mt = 0; mt < 4; mt++)
#pragma unroll
        for (int nt = 0; nt < 4; nt++)
#pragma unroll
            for (int e = 0; e < 4; e++) acc[mt][nt][e] = 0.f;

    const int g = lane >> 3, r = lane & 7;
    const int a_row = ((g & 1) << 3) + r;
    const int a_col = (g >> 1) << 3;
    const int b_row = ((g >> 1) << 3) + r;
    const int b_col = (g & 1) << 3;

    load_chunk(0, 0);

    for (int c = 0; c < 4; c++) {
        const int st = c & 1;
        if (c < 3) {
            load_chunk(st ^ 1, (c + 1) * KCH);
            cp_wait<1>();
        } else {
            cp_wait<0>();
        }
        __syncthreads();

        const unsigned stA = sb + st * STAGE_BYTES;
        const unsigned bAhi = stA;
        const unsigned bAlo = stA + ARR_BYTES;
        const unsigned bBhi = stA + 2 * ARR_BYTES;
        const unsigned bBlo = stA + 3 * ARR_BYTES;

#pragma unroll
        for (int ks = 0; ks < 2; ks++) {
            const int kcol = ks * 16;
            unsigned bh[4][2], bl[4][2];
            {
                unsigned off0 = (unsigned)((n_off + b_row) * TLD + kcol + b_col) * 2;
                unsigned off1 = (unsigned)((n_off + 16 + b_row) * TLD + kcol + b_col) * 2;
                ldsm4(bh[0][0], bh[0][1], bh[1][0], bh[1][1], bBhi + off0);
                ldsm4(bh[2][0], bh[2][1], bh[3][0], bh[3][1], bBhi + off1);
                ldsm4(bl[0][0], bl[0][1], bl[1][0], bl[1][1], bBlo + off0);
                ldsm4(bl[2][0], bl[2][1], bl[3][0], bl[3][1], bBlo + off1);
            }
#pragma unroll
            for (int mt = 0; mt < 4; mt++) {
                unsigned ah[4], al[4];
                unsigned aoff = (unsigned)((m_off + mt * 16 + a_row) * TLD + kcol + a_col) * 2;
                ldsm4(ah[0], ah[1], ah[2], ah[3], bAhi + aoff);
                ldsm4(al[0], al[1], al[2], al[3], bAlo + aoff);
#pragma unroll
                for (int nt = 0; nt < 4; nt++) {
                    mma16816(acc[mt][nt], ah, bh[nt]);
                    mma16816(acc[mt][nt], ah, bl[nt]);
                    mma16816(acc[mt][nt], al, bh[nt]);
                }
            }
        }
        __syncthreads();
    }

    // Direct store (stream order).
    const int dr = lane >> 2;
    const int dc = (lane & 3) * 2;
#pragma unroll
    for (int mt = 0; mt < 4; mt++) {
#pragma unroll
        for (int nt = 0; nt < 4; nt++) {
            size_t base0 = (size_t)(i0 + m_off + mt * 16 + dr) * BSZ + j0 + n_off + nt * 8 + dc;
            *(float2*)(g_S + base0) = make_float2(acc[mt][nt][0], acc[mt][nt][1]);
            *(float2*)(g_S + base0 + 8 * BSZ) = make_float2(acc[mt][nt][2], acc[mt][nt][3]);
        }
    }

    // Epilogue mirror (off-diagonal): stage D in smem, write transpose coalesced.
    if (blockIdx.x != blockIdx.y) {
        float* fs = (float*)smem;      // 128 x 133 floats = 68096 B, stride 133 (cf)
#pragma unroll
        for (int mt = 0; mt < 4; mt++) {
#pragma unroll
            for (int nt = 0; nt < 4; nt++) {
                int row = m_off + mt * 16 + dr;
                int col = n_off + nt * 8 + dc;
                fs[row * 133 + col]           = acc[mt][nt][0];
                fs[row * 133 + col + 1]       = acc[mt][nt][1];
                fs[(row + 8) * 133 + col]     = acc[mt][nt][2];
                fs[(row + 8) * 133 + col + 1] = acc[mt][nt][3];
            }
        }
        __syncthreads();
#pragma unroll
        for (int q = 0; q < 64; q++) {
            int idx = q * 256 + tid;
            int cc = idx & 127;        // original row  (lane-consecutive -> coalesced)
            int rr = idx >> 7;         // original col
            g_S[(size_t)(j0 + rr) * BSZ + i0 + cc] = fs[cc * 133 + rr];
        }
    }
}

// ---------------- Kernel 2: per-row stats + exact top-200 radix select ----
__device__ __forceinline__ float key2f(unsigned int k) {
    unsigned int u = (k & 0x80000000u) ? (k ^ 0x80000000u) : ~k;
    return __uint_as_float(u);
}

#define CAND_MAX 2048
#define PLIST_MAX 288

__global__ __launch_bounds__(256) void row_kernel(const int* __restrict__ labels,
                                                  float* __restrict__ out) {
    __shared__ unsigned int key[BSZ];            // 16 KB
    __shared__ unsigned int cand[CAND_MAX];      // 8 KB
    __shared__ unsigned short plist[PLIST_MAX];  // positives (indices)
    __shared__ float rf[256];
    __shared__ float rf2[256];
    __shared__ int   ri[256];
    __shared__ int   hist4[4][256];
    __shared__ unsigned int s_sel;
    __shared__ int s_krem, s_np, s_nc, s_last;

    const int tid = threadIdx.x;
    const int wid = tid >> 5;
    const int i = blockIdx.x;
    const int labi = labels[i];
    const float* srow = g_S + (size_t)i * BSZ;

    // init
#pragma unroll
    for (int q = 0; q < 4; q++) hist4[q][tid] = 0;
    if (tid == 0) { s_np = 0; s_nc = 0; }
    __syncthreads();

    // === Sweep 1: load row, keys, max, byte0 histogram, positive list ===
    float mx = -1e30f;
    int* myh = hist4[wid >> 1];
#pragma unroll
    for (int t = 0; t < 4; t++) {
        int j4 = tid + t * 256;
        float4 v = ((const float4*)srow)[j4];
        int4 lb = ((const int4*)labels)[j4];
        float vs[4] = {v.x, v.y, v.z, v.w};
        int ls[4] = {lb.x, lb.y, lb.z, lb.w};
#pragma unroll
        for (int e = 0; e < 4; e++) {
            float f = vs[e];
            mx = fmaxf(mx, f);
            unsigned int u = __float_as_uint(f);
            u = (u & 0x80000000u) ? ~u : (u | 0x80000000u);
            key[j4 * 4 + e] = u;
            unsigned int b = u >> 24;
            unsigned int m = __match_any_sync(0xFFFFFFFFu, b);   // non-divergent
            if ((tid & 31) == (__ffs(m) - 1)) atomicAdd(&myh[b], __popc(m));
            if (ls[e] == labi) {
                int idx = atomicAdd(&s_np, 1);
                if (idx < PLIST_MAX) plist[idx] = (unsigned short)(j4 * 4 + e);
            }
        }
    }
    rf[tid] = mx;
    __syncthreads();
    for (int s = 128; s; s >>= 1) {
        if (tid < s) rf[tid] = fmaxf(rf[tid], rf[tid + s]);
        __syncthreads();
    }
    const float smax = rf[0];
    const int np = s_np;
    __syncthreads();

    // === Positives: sums + zero keys + hist subtract ===
    float sl = 0.f, se = 0.f;
    int cnt = 0;
    if (np <= PLIST_MAX) {
        for (int t = tid; t < np; t += 256) {
            int j = plist[t];
            unsigned int u = key[j];
            atomicSub(&hist4[0][u >> 24], 1);
            key[j] = 0u;
            if (j != i) {
                float s = key2f(u);
                float lg = (s - smax) * 10.f;
                sl += lg;
                se += expf(lg);
                cnt++;
            }
        }
    } else {
        // fallback: full sweep
#pragma unroll
        for (int t = 0; t < 16; t++) {
            int j = tid + t * 256;
            if (labels[j] == labi) {
                unsigned int u = key[j];
                atomicSub(&hist4[0][u >> 24], 1);
                key[j] = 0u;
                if (j != i) {
                    float s = key2f(u);
                    float lg = (s - smax) * 10.f;
                    sl += lg;
                    se += expf(lg);
                    cnt++;
                }
            }
        }
    }
    rf[tid] = sl; rf2[tid] = se; ri[tid] = cnt;
    __syncthreads();
    for (int s = 128; s; s >>= 1) {
        if (tid < s) {
            rf[tid]  += rf[tid + s];
            rf2[tid] += rf2[tid + s];
            ri[tid]  += ri[tid + s];
        }
        __syncthreads();
    }
    const float sl_tot = rf[0];
    const float se_tot = rf2[0];
    const int   cnt_tot = ri[0];
    __syncthreads();

    // warp-0 suffix-scan bucket selection over hist4 sums
    int krem = 200;
#define SELECT_BUCKET()                                                         \
    do {                                                                        \
        if (tid < 32) {                                                         \
            int h[8], suf[8];                                                   \
            _Pragma("unroll")                                                   \
            for (int e = 0; e < 8; e++)                                         \
                h[e] = hist4[0][tid * 8 + e] + hist4[1][tid * 8 + e]            \
                     + hist4[2][tid * 8 + e] + hist4[3][tid * 8 + e];           \
            int run = 0;                                                        \
            _Pragma("unroll")                                                   \
            for (int e = 7; e >= 0; e--) { run += h[e]; suf[e] = run; }         \
            int v = run;                                                        \
            _Pragma("unroll")                                                   \
            for (int off = 1; off < 32; off <<= 1) {                            \
                int o = __shfl_down_sync(0xFFFFFFFFu, v, off);                  \
                if (tid + off < 32) v += o;                                     \
            }                                                                   \
            const int carry = v - run;                                          \
            _Pragma("unroll")                                                   \
            for (int e = 0; e < 8; e++) {                                       \
                int S   = suf[e] + carry;                                       \
                int Sab = (e < 7) ? (suf[e + 1] + carry) : carry;               \
                if (S >= krem && Sab < krem) {                                  \
                    s_sel = (unsigned int)(tid * 8 + e);                        \
                    s_krem = krem - Sab;                                        \
                }                                                               \
            }                                                                   \
        }                                                                       \
        __syncthreads();                                                        \
    } while (0)

#define CLEAR_HIST()                                                            \
    do {                                                                        \
        _Pragma("unroll")                                                       \
        for (int q = 0; q < 4; q++) hist4[q][tid] = 0;                          \
        __syncthreads();                                                        \
    } while (0)

    SELECT_BUCKET();
    const unsigned int sel0 = s_sel;
    krem = s_krem;
    __syncthreads();
    CLEAR_HIST();

    // === Sweep 2 (pass 1): exp for b0>sel0, compact b0==sel0, hist byte1 ===
    float sg = 0.f;
#pragma unroll
    for (int t = 0; t < 16; t++) {
        unsigned int u = key[tid + t * 256];
        unsigned int b0 = u >> 24;
        if (b0 > sel0) {
            sg += expf((key2f(u) - smax) * 10.f);
        } else if (b0 == sel0) {
            int idx = atomicAdd(&s_nc, 1);
            if (idx < CAND_MAX) cand[idx] = u;
            atomicAdd(&myh[(u >> 16) & 255], 1);
        }
    }
    __syncthreads();
    const int nc = s_nc;
    const bool candOK = (nc <= CAND_MAX);

    SELECT_BUCKET();
    const unsigned int sel1 = s_sel;
    krem = s_krem;
    __syncthreads();

    unsigned int pivot;
    if (candOK) {
        // pass 2 over candidates
        CLEAR_HIST();
        for (int t = tid; t < nc; t += 256) {
            unsigned int u = cand[t];
            unsigned int b1 = (u >> 16) & 255;
            if (b1 > sel1) sg += expf((key2f(u) - smax) * 10.f);
            else if (b1 == sel1) atomicAdd(&hist4[0][(u >> 8) & 255], 1);
        }
        __syncthreads();
        SELECT_BUCKET();
        const unsigned int sel2 = s_sel;
        krem = s_krem;
        __syncthreads();

        // pass 3 over candidates
        CLEAR_HIST();
        for (int t = tid; t < nc; t += 256) {
            unsigned int u = cand[t];
            if (((u >> 16) & 255) == sel1) {
                unsigned int b2 = (u >> 8) & 255;
                if (b2 > sel2) sg += expf((key2f(u) - smax) * 10.f);
                else if (b2 == sel2) atomicAdd(&hist4[0][u & 255], 1);
            }
        }
        __syncthreads();
        SELECT_BUCKET();
        const unsigned int sel3 = s_sel;
        krem = s_krem;
        __syncthreads();

        pivot = (sel0 << 24) | (sel1 << 16) | (sel2 << 8) | sel3;

        // final partial: full-prefix matches strictly above sel3
        for (int t = tid; t < nc; t += 256) {
            unsigned int u = cand[t];
            if (((u >> 16) & 255) == sel1 && ((u >> 8) & 255) == sel2 && (u & 255) > sel3)
                sg += expf((key2f(u) - smax) * 10.f);
        }
    } else {
        // fallback: full-sweep passes 2..3 + full final sweep (sg rebuilt)
        unsigned int prefix = (sel0 << 24) | (sel1 << 16);
        CLEAR_HIST();
#pragma unroll
        for (int t = 0; t < 16; t++) {
            unsigned int u = key[tid + t * 256];
            if ((u ^ prefix) >> 16 == 0) atomicAdd(&myh[(u >> 8) & 255], 1);
        }
        __syncthreads();
        SELECT_BUCKET();
        prefix |= s_sel << 8;
        krem = s_krem;
        __syncthreads();
        CLEAR_HIST();
#pragma unroll
        for (int t = 0; t < 16; t++) {
            unsigned int u = key[tid + t * 256];
            if ((u ^ prefix) >> 8 == 0) atomicAdd(&myh[u & 255], 1);
        }
        __syncthreads();
        SELECT_BUCKET();
        pivot = prefix | s_sel;
        krem = s_krem;
        __syncthreads();
        sg = 0.f;
#pragma unroll
        for (int t = 0; t < 16; t++) {
            unsigned int u = key[tid + t * 256];
            if (u > pivot) sg += expf((key2f(u) - smax) * 10.f);
        }
    }

    rf[tid] = sg;
    __syncthreads();
    for (int s = 128; s; s >>= 1) { if (tid < s) rf[tid] += rf[tid + s]; __syncthreads(); }

    if (tid == 0) {
        float sg_tot = rf[0] + (float)krem * expf((key2f(pivot) - smax) * 10.f);
        float denom = se_tot + sg_tot;
        bool valid = (labi > 0) && (cnt_tot > 0);
        float per = 0.f;
        if (valid) per = -2.f * (sl_tot / (float)cnt_tot - logf(denom));
        g_row[i] = per;
        g_valid[i] = valid ? 1 : 0;
        __threadfence();
        int v = atomicAdd(&g_done, 1);
        s_last = (v == BSZ - 1);
    }
    __syncthreads();

    // last CTA: deterministic final reduction
    if (s_last) {
        if (tid == 0) g_done = 0;   // self-reset for graph replay
        __threadfence();
        float s = 0.f;
        int c = 0;
        for (int j = tid; j < BSZ; j += 256) {
            s += g_row[j];
            c += g_valid[j];
        }
        rf[tid] = s; ri[tid] = c;
        __syncthreads();
        for (int k = 128; k; k >>= 1) {
            if (tid < k) { rf[tid] += rf[tid + k]; ri[tid] += ri[tid + k]; }
            __syncthreads();
        }
        if (tid == 0) out[0] = rf[0] / (float)ri[0];
    }
}

// --------------------------------------------------------------------------
extern "C" void kernel_launch(void* const* d_in, const int* in_sizes, int n_in,
                              void* d_out, int out_size) {
    const float* F = (const float*)d_in[0];       // [4096, 1, 128] fp32
    const int* labels = (const int*)d_in[1];      // [4096] int32
    (void)in_sizes; (void)n_in; (void)out_size;

    cudaFuncSetAttribute(gemm_mma_kernel,
                         cudaFuncAttributeMaxDynamicSharedMemorySize, SMEM_GEMM);

    convert_kernel<<<512, 256>>>(F);
    dim3 g(32, 32);
    gemm_mma_kernel<<<g, 256, SMEM_GEMM>>>();   // upper tiles + epilogue mirror
    row_kernel<<<BSZ, 256>>>(labels, (float*)d_out);
}